// round 8
// baseline (speedup 1.0000x reference)
#include <cuda_runtime.h>
#include <cuda_fp16.h>
#include <mma.h>
#include <cuda_pipeline.h>

using namespace nvcuda;

constexpr int L_ = 2048, H_ = 8, GSTR = 512;
constexpr int LDH = 72;    // f16 tile leading dim (halves) -> conflict-free ldmatrix
constexpr int LDF = 68;    // f32 score tile leading dim
constexpr int LDS_ = 68;   // f32 staging tile leading dim
// smem byte offsets
constexpr int OQH = 0,     OQL = 9216,  OKH = 18432;
constexpr int OVH = 27648, OVL = 36864, OPH = 46080;
constexpr int OSF = 55296, ODS = 72704, OSK = 72960, OSV = 90368;
constexpr int SM_BYTES = 107776;

// Q only: gmem f32 -> hi/lo f16 smem tiles. t in [0,256).
__device__ __forceinline__ void fill_q(const float* g, __half* hi, __half* lo, int t)
{
    #pragma unroll
    for (int i = 0; i < 2; i++) {
        int ck = i * 256 + t;
        int row = ck >> 3, ch = (ck & 7) * 8;
        const float* s = g + (size_t)row * GSTR + ch;
        float4 x = *(const float4*)s;
        float4 y = *(const float4*)(s + 4);
        float xs[8] = {x.x, x.y, x.z, x.w, y.x, y.y, y.z, y.w};
        __align__(16) __half2 hh[4];
        __align__(16) __half2 ll[4];
        #pragma unroll
        for (int j = 0; j < 4; j++) {
            __half2 a = __floats2half2_rn(xs[2 * j], xs[2 * j + 1]);
            float2 f = __half22float2(a);
            hh[j] = a;
            ll[j] = __floats2half2_rn(xs[2 * j] - f.x, xs[2 * j + 1] - f.y);
        }
        *(uint4*)&hi[row * LDH + ch] = *(uint4*)hh;
        *(uint4*)&lo[row * LDH + ch] = *(uint4*)ll;
    }
}

// async-prefetch a 64x64 f32 tile into smem staging
__device__ __forceinline__ void prefetch_tile(const float* g, float* stage, int t)
{
    #pragma unroll
    for (int i = 0; i < 4; i++) {
        int s = i * 256 + t;               // 1024 float4 segments
        int row = s >> 4, c4 = (s & 15) * 4;
        __pipeline_memcpy_async(&stage[row * LDS_ + c4],
                                g + (size_t)row * GSTR + c4, 16);
    }
}

__global__ void __launch_bounds__(256, 2)
attn_kernel(const float* __restrict__ Q, const float* __restrict__ K,
            const float* __restrict__ V, const float* __restrict__ tau,
            const float* __restrict__ delta, float* __restrict__ O)
{
    extern __shared__ char smc[];
    __half* Qhi = (__half*)(smc + OQH);
    __half* Qlo = (__half*)(smc + OQL);
    __half* Khi = (__half*)(smc + OKH);
    __half* Vhi = (__half*)(smc + OVH);
    __half* Vlo = (__half*)(smc + OVL);
    __half* Phi = (__half*)(smc + OPH);
    float*  Sf  = (float*)(smc + OSF);
    float*  Ds  = (float*)(smc + ODS);
    float*  stK = (float*)(smc + OSK);
    float*  stV = (float*)(smc + OSV);

    const int qt = blockIdx.x, bh = blockIdx.y, b = bh >> 3, h = bh & 7;
    const int t = threadIdx.x, w = t >> 5;
    const int wr = w >> 1, wc = w & 1;       // warp block: rows [16wr,+16), cols [32wc,+32)
    const int r = t >> 2, cb = (t & 3) * 16; // softmax: row r, 16 cols from cb

    const float stl = 0.125f * tau[b];       // natural-log domain
    const float sdl = 0.125f;

    const float* qg = Q + ((size_t)(b * L_ + qt * 64) * H_ + h) * 64;
    const float* kg = K + ((size_t)(b * L_) * H_ + h) * 64;
    const float* vg = V + ((size_t)(b * L_) * H_ + h) * 64;
    const float* dg = delta + (size_t)b * L_;

    fill_q(qg, Qhi, Qlo, t);
    prefetch_tile(kg, stK, t);
    prefetch_tile(vg, stV, t);
    __pipeline_commit();

    wmma::fragment<wmma::accumulator, 16, 16, 16, float> oacc[2];
    wmma::fill_fragment(oacc[0], 0.0f);
    wmma::fill_fragment(oacc[1], 0.0f);
    float lsum = 0.0f;

    for (int kt = 0; kt <= qt; kt++) {
        __pipeline_wait_prior(0);
        __syncthreads();

        // ---- convert staged f32 tiles to f16 (K: hi only; V: hi+lo) ----
        #pragma unroll
        for (int i = 0; i < 2; i++) {
            int ck = i * 256 + t;
            int row = ck >> 3, ch = (ck & 7) * 8;
            {   // K -> hi
                const float* s = &stK[row * LDS_ + ch];
                float4 x = *(const float4*)s;
                float4 y = *(const float4*)(s + 4);
                __align__(16) __half2 hh[4];
                hh[0] = __floats2half2_rn(x.x, x.y);
                hh[1] = __floats2half2_rn(x.z, x.w);
                hh[2] = __floats2half2_rn(y.x, y.y);
                hh[3] = __floats2half2_rn(y.z, y.w);
                *(uint4*)&Khi[row * LDH + ch] = *(uint4*)hh;
            }
            {   // V -> hi + lo
                const float* s = &stV[row * LDS_ + ch];
                float4 x = *(const float4*)s;
                float4 y = *(const float4*)(s + 4);
                float xs[8] = {x.x, x.y, x.z, x.w, y.x, y.y, y.z, y.w};
                __align__(16) __half2 hh[4];
                __align__(16) __half2 ll[4];
                #pragma unroll
                for (int j = 0; j < 4; j++) {
                    __half2 a = __floats2half2_rn(xs[2 * j], xs[2 * j + 1]);
                    float2 f = __half22float2(a);
                    hh[j] = a;
                    ll[j] = __floats2half2_rn(xs[2 * j] - f.x, xs[2 * j + 1] - f.y);
                }
                *(uint4*)&Vhi[row * LDH + ch] = *(uint4*)hh;
                *(uint4*)&Vlo[row * LDH + ch] = *(uint4*)ll;
            }
        }
        if (t < 64) Ds[t] = dg[kt * 64 + t] * sdl;
        __syncthreads();

        // stage buffers free now: prefetch next tile behind compute
        if (kt < qt) {
            prefetch_tile(kg + (size_t)(kt + 1) * 64 * GSTR, stK, t);
            prefetch_tile(vg + (size_t)(kt + 1) * 64 * GSTR, stV, t);
            __pipeline_commit();
        }

        // ---- QK^T: (qh+ql)*kh -> exact in q. Warp: 16x32 block ----
        {
            wmma::fragment<wmma::accumulator, 16, 16, 16, float> acc[2];
            wmma::fill_fragment(acc[0], 0.0f);
            wmma::fill_fragment(acc[1], 0.0f);
            #pragma unroll
            for (int k = 0; k < 4; k++) {
                wmma::fragment<wmma::matrix_a, 16, 16, 16, __half, wmma::row_major> aH, aL;
                wmma::load_matrix_sync(aH, Qhi + wr * 16 * LDH + k * 16, LDH);
                wmma::load_matrix_sync(aL, Qlo + wr * 16 * LDH + k * 16, LDH);
                #pragma unroll
                for (int n = 0; n < 2; n++) {
                    wmma::fragment<wmma::matrix_b, 16, 16, 16, __half, wmma::col_major> bH;
                    wmma::load_matrix_sync(bH, Khi + (wc * 32 + n * 16) * LDH + k * 16, LDH);
                    wmma::mma_sync(acc[n], aH, bH, acc[n]);
                    wmma::mma_sync(acc[n], aL, bH, acc[n]);
                }
            }
            wmma::store_matrix_sync(Sf + wr * 16 * LDF + wc * 32,      acc[0], LDF, wmma::mem_row_major);
            wmma::store_matrix_sync(Sf + wr * 16 * LDF + wc * 32 + 16, acc[1], LDF, wmma::mem_row_major);
        }
        __syncthreads();

        // ---- softmax (bounded logits, no max-sub): row r, cols [cb,cb+16) ----
        {
            const int qr = qt * 64 + r;
            const int s0 = kt * 64;
            const bool diag = (kt == qt);
            float psum = 0.0f;
            #pragma unroll
            for (int j = 0; j < 16; j += 4) {
                float4 sv = *(const float4*)&Sf[r * LDF + cb + j];
                float z0 = sv.x * stl + Ds[cb + j];
                float z1 = sv.y * stl + Ds[cb + j + 1];
                float z2 = sv.z * stl + Ds[cb + j + 2];
                float z3 = sv.w * stl + Ds[cb + j + 3];
                if (diag) {
                    if (s0 + cb + j     > qr) z0 = -1e30f;
                    if (s0 + cb + j + 1 > qr) z1 = -1e30f;
                    if (s0 + cb + j + 2 > qr) z2 = -1e30f;
                    if (s0 + cb + j + 3 > qr) z3 = -1e30f;
                }
                float p0 = __expf(z0), p1 = __expf(z1);
                float p2 = __expf(z2), p3 = __expf(z3);
                psum += (p0 + p1) + (p2 + p3);
                __align__(8) __half2 hp[2];
                hp[0] = __floats2half2_rn(p0, p1);
                hp[1] = __floats2half2_rn(p2, p3);
                *(uint2*)&Phi[r * LDH + cb + j] = *(uint2*)hp;
            }
            lsum += psum;
        }
        __syncthreads();

        // ---- P @ V: ph*(vh+vl) -> exact in v. Persistent O fragments ----
        #pragma unroll
        for (int k = 0; k < 4; k++) {
            wmma::fragment<wmma::matrix_a, 16, 16, 16, __half, wmma::row_major> pH;
            wmma::load_matrix_sync(pH, Phi + wr * 16 * LDH + k * 16, LDH);
            #pragma unroll
            for (int n = 0; n < 2; n++) {
                wmma::fragment<wmma::matrix_b, 16, 16, 16, __half, wmma::row_major> vH, vL;
                wmma::load_matrix_sync(vH, Vhi + k * 16 * LDH + wc * 32 + n * 16, LDH);
                wmma::load_matrix_sync(vL, Vlo + k * 16 * LDH + wc * 32 + n * 16, LDH);
                wmma::mma_sync(oacc[n], pH, vH, oacc[n]);
                wmma::mma_sync(oacc[n], pH, vL, oacc[n]);
            }
        }
    }

    // ---- epilogue ----
    wmma::store_matrix_sync(Sf + wr * 16 * LDF + wc * 32,      oacc[0], LDF, wmma::mem_row_major);
    wmma::store_matrix_sync(Sf + wr * 16 * LDF + wc * 32 + 16, oacc[1], LDF, wmma::mem_row_major);
    __syncthreads();

    lsum += __shfl_xor_sync(0xFFFFFFFFu, lsum, 1);
    lsum += __shfl_xor_sync(0xFFFFFFFFu, lsum, 2);
    const float inv = 1.0f / lsum;

    float* ob = O + ((size_t)(b * L_ + qt * 64 + r) * H_ + h) * 64 + cb;
    #pragma unroll
    for (int j = 0; j < 16; j += 4) {
        float4 sv = *(const float4*)&Sf[r * LDF + cb + j];
        float4 v;
        v.x = sv.x * inv; v.y = sv.y * inv;
        v.z = sv.z * inv; v.w = sv.w * inv;
        *(float4*)&ob[j] = v;
    }
}

extern "C" void kernel_launch(void* const* d_in, const int* in_sizes, int n_in,
                              void* d_out, int out_size)
{
    cudaFuncSetAttribute(attn_kernel,
                         cudaFuncAttributeMaxDynamicSharedMemorySize, SM_BYTES);
    dim3 grid(L_ / 64, 32);
    attn_kernel<<<grid, 256, SM_BYTES>>>(
        (const float*)d_in[0], (const float*)d_in[1], (const float*)d_in[2],
        (const float*)d_in[3], (const float*)d_in[4], (float*)d_out);
}

// round 10
// speedup vs baseline: 1.6855x; 1.6855x over previous
#include <cuda_runtime.h>
#include <cuda_fp16.h>
#include <mma.h>

using namespace nvcuda;

constexpr int L_ = 2048, H_ = 8, GSTR = 512;
constexpr int LDH = 72;   // f16 tile leading dim (halves)
constexpr int LDF = 68;   // f32 tile leading dim
constexpr int OQH = 0,     OQL = 9216,  OKH = 18432;
constexpr int OVH = 27648, OVL = 36864, OPH = 46080;
constexpr int OSF = 55296, ODS = 72704;
constexpr int SM_BYTES = 72960;

// gmem f32 64x64 -> hi+lo f16 tiles. t in [0,256).
__device__ __forceinline__ void fill_hilo(const float* g, __half* hi, __half* lo, int t)
{
    #pragma unroll
    for (int i = 0; i < 2; i++) {
        int ck = i * 256 + t;
        int row = ck >> 3, ch = (ck & 7) * 8;
        const float* s = g + (size_t)row * GSTR + ch;
        float4 x = *(const float4*)s;
        float4 y = *(const float4*)(s + 4);
        float xs[8] = {x.x, x.y, x.z, x.w, y.x, y.y, y.z, y.w};
        __align__(16) __half2 hh[4];
        __align__(16) __half2 ll[4];
        #pragma unroll
        for (int j = 0; j < 4; j++) {
            __half2 a = __floats2half2_rn(xs[2 * j], xs[2 * j + 1]);
            float2 f = __half22float2(a);
            hh[j] = a;
            ll[j] = __floats2half2_rn(xs[2 * j] - f.x, xs[2 * j + 1] - f.y);
        }
        *(uint4*)&hi[row * LDH + ch] = *(uint4*)hh;
        *(uint4*)&lo[row * LDH + ch] = *(uint4*)ll;
    }
}

// gmem f32 64x64 -> hi-only f16 tile. t in [0,256).
__device__ __forceinline__ void fill_hi(const float* g, __half* hi, int t)
{
    #pragma unroll
    for (int i = 0; i < 2; i++) {
        int ck = i * 256 + t;
        int row = ck >> 3, ch = (ck & 7) * 8;
        const float* s = g + (size_t)row * GSTR + ch;
        float4 x = *(const float4*)s;
        float4 y = *(const float4*)(s + 4);
        __align__(16) __half2 hh[4];
        hh[0] = __floats2half2_rn(x.x, x.y);
        hh[1] = __floats2half2_rn(x.z, x.w);
        hh[2] = __floats2half2_rn(y.x, y.y);
        hh[3] = __floats2half2_rn(y.z, y.w);
        *(uint4*)&hi[row * LDH + ch] = *(uint4*)hh;
    }
}

__global__ void __launch_bounds__(256, 2)
attn_kernel(const float* __restrict__ Q, const float* __restrict__ K,
            const float* __restrict__ V, const float* __restrict__ tau,
            const float* __restrict__ delta, float* __restrict__ O)
{
    extern __shared__ char smc[];
    __half* Qhi = (__half*)(smc + OQH);
    __half* Qlo = (__half*)(smc + OQL);
    __half* Khi = (__half*)(smc + OKH);
    __half* Vhi = (__half*)(smc + OVH);
    __half* Vlo = (__half*)(smc + OVL);
    __half* Phi = (__half*)(smc + OPH);
    float*  Sf  = (float*)(smc + OSF);
    float*  Ds  = (float*)(smc + ODS);

    const int qt = blockIdx.x, bh = blockIdx.y, b = bh >> 3, h = bh & 7;
    const int t = threadIdx.x, w = t >> 5;
    const int wr = w >> 1, wc = w & 1;       // warp block: rows [16wr,+16), cols [32wc,+32)
    const int r = t >> 2, cb = (t & 3) * 16; // softmax: row r, cols [cb,cb+16)

    const float stl = 0.125f * tau[b];       // natural-log domain (__expf)
    const float sdl = 0.125f;

    const float* qg = Q + ((size_t)(b * L_ + qt * 64) * H_ + h) * 64;
    const float* kg = K + ((size_t)(b * L_) * H_ + h) * 64;
    const float* vg = V + ((size_t)(b * L_) * H_ + h) * 64;
    const float* dg = delta + (size_t)b * L_;

    fill_hilo(qg, Qhi, Qlo, t);

    wmma::fragment<wmma::accumulator, 16, 16, 16, float> oacc[2];
    wmma::fill_fragment(oacc[0], 0.0f);
    wmma::fill_fragment(oacc[1], 0.0f);
    float lsum = 0.0f;

    for (int kt = 0; kt <= qt; kt++) {
        __syncthreads();
        fill_hi(kg + (size_t)kt * 64 * GSTR, Khi, t);
        fill_hilo(vg + (size_t)kt * 64 * GSTR, Vhi, Vlo, t);
        if (t < 64) Ds[t] = dg[kt * 64 + t] * sdl;
        __syncthreads();

        // ---- QK^T: (Qhi+Qlo)*Khi, exact in q. Warp: 16x32 block ----
        {
            wmma::fragment<wmma::accumulator, 16, 16, 16, float> acc[2];
            wmma::fill_fragment(acc[0], 0.0f);
            wmma::fill_fragment(acc[1], 0.0f);
            #pragma unroll
            for (int k = 0; k < 4; k++) {
                wmma::fragment<wmma::matrix_a, 16, 16, 16, __half, wmma::row_major> aH, aL;
                wmma::load_matrix_sync(aH, Qhi + wr * 16 * LDH + k * 16, LDH);
                wmma::load_matrix_sync(aL, Qlo + wr * 16 * LDH + k * 16, LDH);
                #pragma unroll
                for (int n = 0; n < 2; n++) {
                    wmma::fragment<wmma::matrix_b, 16, 16, 16, __half, wmma::col_major> bH;
                    wmma::load_matrix_sync(bH, Khi + (wc * 32 + n * 16) * LDH + k * 16, LDH);
                    wmma::mma_sync(acc[n], aH, bH, acc[n]);
                    wmma::mma_sync(acc[n], aL, bH, acc[n]);
                }
            }
            wmma::store_matrix_sync(Sf + wr * 16 * LDF + wc * 32,      acc[0], LDF, wmma::mem_row_major);
            wmma::store_matrix_sync(Sf + wr * 16 * LDF + wc * 32 + 16, acc[1], LDF, wmma::mem_row_major);
        }
        __syncthreads();

        // ---- softmax (bounded logits, no max-sub): row r, cols [cb,cb+16) ----
        {
            const int qr = qt * 64 + r;
            const int s0 = kt * 64;
            const bool diag = (kt == qt);
            float psum = 0.0f;
            #pragma unroll
            for (int j = 0; j < 16; j += 4) {
                float4 sv = *(const float4*)&Sf[r * LDF + cb + j];
                float z0 = sv.x * stl + Ds[cb + j];
                float z1 = sv.y * stl + Ds[cb + j + 1];
                float z2 = sv.z * stl + Ds[cb + j + 2];
                float z3 = sv.w * stl + Ds[cb + j + 3];
                if (diag) {
                    if (s0 + cb + j     > qr) z0 = -1e30f;
                    if (s0 + cb + j + 1 > qr) z1 = -1e30f;
                    if (s0 + cb + j + 2 > qr) z2 = -1e30f;
                    if (s0 + cb + j + 3 > qr) z3 = -1e30f;
                }
                float p0 = __expf(z0), p1 = __expf(z1);
                float p2 = __expf(z2), p3 = __expf(z3);
                psum += (p0 + p1) + (p2 + p3);
                __align__(8) __half2 hp[2];
                hp[0] = __floats2half2_rn(p0, p1);
                hp[1] = __floats2half2_rn(p2, p3);
                *(uint2*)&Phi[r * LDH + cb + j] = *(uint2*)hp;
            }
            lsum += psum;
        }
        __syncthreads();

        // ---- P @ V: Phi*(Vhi+Vlo), exact in v. Persistent O fragments ----
        #pragma unroll
        for (int k = 0; k < 4; k++) {
            wmma::fragment<wmma::matrix_a, 16, 16, 16, __half, wmma::row_major> pH;
            wmma::load_matrix_sync(pH, Phi + wr * 16 * LDH + k * 16, LDH);
            #pragma unroll
            for (int n = 0; n < 2; n++) {
                wmma::fragment<wmma::matrix_b, 16, 16, 16, __half, wmma::row_major> vH, vL;
                wmma::load_matrix_sync(vH, Vhi + k * 16 * LDH + wc * 32 + n * 16, LDH);
                wmma::load_matrix_sync(vL, Vlo + k * 16 * LDH + wc * 32 + n * 16, LDH);
                wmma::mma_sync(oacc[n], pH, vH, oacc[n]);
                wmma::mma_sync(oacc[n], pH, vL, oacc[n]);
            }
        }
    }

    // ---- epilogue ----
    wmma::store_matrix_sync(Sf + wr * 16 * LDF + wc * 32,      oacc[0], LDF, wmma::mem_row_major);
    wmma::store_matrix_sync(Sf + wr * 16 * LDF + wc * 32 + 16, oacc[1], LDF, wmma::mem_row_major);
    __syncthreads();

    lsum += __shfl_xor_sync(0xFFFFFFFFu, lsum, 1);
    lsum += __shfl_xor_sync(0xFFFFFFFFu, lsum, 2);
    const float inv = 1.0f / lsum;

    float* ob = O + ((size_t)(b * L_ + qt * 64 + r) * H_ + h) * 64 + cb;
    #pragma unroll
    for (int j = 0; j < 16; j += 4) {
        float4 sv = *(const float4*)&Sf[r * LDF + cb + j];
        float4 v;
        v.x = sv.x * inv; v.y = sv.y * inv;
        v.z = sv.z * inv; v.w = sv.w * inv;
        *(float4*)&ob[j] = v;
    }
}

extern "C" void kernel_launch(void* const* d_in, const int* in_sizes, int n_in,
                              void* d_out, int out_size)
{
    cudaFuncSetAttribute(attn_kernel,
                         cudaFuncAttributeMaxDynamicSharedMemorySize, SM_BYTES);
    dim3 grid(L_ / 64, 32);
    attn_kernel<<<grid, 256, SM_BYTES>>>(
        (const float*)d_in[0], (const float*)d_in[1], (const float*)d_in[2],
        (const float*)d_in[3], (const float*)d_in[4], (float*)d_out);
}